// round 15
// baseline (speedup 1.0000x reference)
#include <cuda_runtime.h>
#include <cuda_bf16.h>

#define TPB   128
#define ROWS  64          // batch rows per CTA; 16 rows per warp (warp-private recurrence)

typedef unsigned int u32;

// ---------- helpers ----------
__device__ __forceinline__ unsigned short f2bf(float f) {
    unsigned short u; asm("cvt.rn.bf16.f32 %0, %1;" : "=h"(u) : "f"(f)); return u;
}
__device__ __forceinline__ float bf2f(unsigned short u) { return __uint_as_float((u32)u << 16); }
__device__ __forceinline__ u32 packbf(unsigned short lo, unsigned short hi) {
    return (u32)lo | ((u32)hi << 16);
}
__device__ __forceinline__ float tanh_hw(float x) {
    float y; asm("tanh.approx.f32 %0, %1;" : "=f"(y) : "f"(x)); return y;
}
__device__ __forceinline__ float sigm(float x) {   // sigma(x) = 0.5 + 0.5*tanh(x/2)
    return fmaf(0.5f, tanh_hw(0.5f * x), 0.5f);
}
// m16n8k16 bf16 MMA, f32 accum (HMMA path on sm_103)
__device__ __forceinline__ void mma16816(float* d, u32 a0, u32 a1, u32 a2, u32 a3,
                                         u32 b0, u32 b1) {
    asm volatile("mma.sync.aligned.m16n8k16.row.col.f32.bf16.bf16.f32 "
                 "{%0,%1,%2,%3}, {%4,%5,%6,%7}, {%8,%9}, {%0,%1,%2,%3};"
                 : "+f"(d[0]), "+f"(d[1]), "+f"(d[2]), "+f"(d[3])
                 : "r"(a0), "r"(a1), "r"(a2), "r"(a3), "r"(b0), "r"(b1));
}

// SMEM byte offsets
#define OFF_UF   0                       // frag-linear U (hi+lo): 32nt x 4kt x 32 lanes x 16B = 65536
#define OFF_SW   65536                   // W[256] f32
#define OFF_SB   (OFF_SW + 1024)         // b[256] f32
#define OFF_SWD  (OFF_SB + 1024)         // Wd[64] f32
#define OFF_SX   (OFF_SWD + 256)         // x[64*5] f32
#define SMEM_BYTES (OFF_SX + 1280)       // 69120 B -> 2 CTAs/SM

__global__ void __launch_bounds__(TPB, 2)
lstm_mma(const float* __restrict__ x, const float* __restrict__ W,
         const float* __restrict__ U, const float* __restrict__ b,
         const float* __restrict__ Wd, const float* __restrict__ bd,
         float* __restrict__ out, int Bn)
{
    extern __shared__ char smem[];
    float* sW  = (float*)(smem + OFF_SW);
    float* sB  = (float*)(smem + OFF_SB);
    float* sWd = (float*)(smem + OFF_SWD);
    float* sX  = (float*)(smem + OFF_SX);

    const int tid  = threadIdx.x;
    const int lane = tid & 31;
    const int wid  = tid >> 5;           // 4 warps, each owns 16 rows
    const int gid  = lane >> 2;
    const int tg   = lane & 3;
    const int r0   = wid * 16;
    const long rowBase = (long)blockIdx.x * ROWS;

    // ---- stage: frag-linear U (hi/lo bf16), W, b, Wd, x ----
    for (int idx = tid; idx < 4096; idx += TPB) {
        const int N  = idx >> 7;         // n-tile 0..31
        const int kt = (idx >> 5) & 3;   // k-tile 0..3
        const int l  = idx & 31;
        const int g2 = l >> 2, t2 = l & 3;
        const int col = N * 8 + g2;
        const int k0  = kt * 16 + 2 * t2;
        const float u0 = U[k0 * 256 + col],       u1 = U[(k0 + 1) * 256 + col];
        const float u8 = U[(k0 + 8) * 256 + col], u9 = U[(k0 + 9) * 256 + col];
        const unsigned short h0 = f2bf(u0), h1 = f2bf(u1), h8 = f2bf(u8), h9 = f2bf(u9);
        const unsigned short l0 = f2bf(u0 - bf2f(h0)), l1 = f2bf(u1 - bf2f(h1));
        const unsigned short l8 = f2bf(u8 - bf2f(h8)), l9 = f2bf(u9 - bf2f(h9));
        uint4 v;
        v.x = packbf(h0, h1);  v.y = packbf(h8, h9);   // B_hi frag regs
        v.z = packbf(l0, l1);  v.w = packbf(l8, l9);   // B_lo frag regs
        *(uint4*)(smem + OFF_UF + idx * 16) = v;
    }
    for (int i = tid; i < 256; i += TPB) { sW[i] = W[i]; sB[i] = b[i]; }
    if (tid < 64) sWd[tid] = Wd[tid];
    {
        const float* xs = x + rowBase * 5;
        for (int i = tid; i < ROWS * 5; i += TPB)
            if (rowBase * 5 + i < (long)Bn * 5) sX[i] = xs[i];
    }
    __syncthreads();                     // the ONLY barrier in the kernel

    float c[32];                         // c[(q<<2)|(e<<1)|r2]
#pragma unroll
    for (int i = 0; i < 32; ++i) c[i] = 0.f;
    u32 hh[8][2], hl[8][2];              // h as next-step A-frags (hi/lo bf16)
    float pd[2] = {0.f, 0.f};            // dense partials (rows gid, gid+8)

#pragma unroll 1
    for (int t = 0; t < 5; ++t) {
        // ---- acc init: z = x*W + b (D-frag layout: [nt][2*r2+e]) ----
        float acc[32][4];
        const float xr0 = sX[(r0 + gid) * 5 + t];
        const float xr1 = sX[(r0 + gid + 8) * 5 + t];
#pragma unroll
        for (int nt = 0; nt < 32; ++nt) {
            const float2 w2 = *(const float2*)(sW + 8 * nt + 2 * tg);
            const float2 b2 = *(const float2*)(sB + 8 * nt + 2 * tg);
            acc[nt][0] = fmaf(xr0, w2.x, b2.x);
            acc[nt][1] = fmaf(xr0, w2.y, b2.y);
            acc[nt][2] = fmaf(xr1, w2.x, b2.x);
            acc[nt][3] = fmaf(xr1, w2.y, b2.y);
        }

        // ---- tensor mainloop: A frags straight from registers (D->A identity) ----
        if (t > 0) {
#pragma unroll
            for (int kt = 0; kt < 4; ++kt) {
                const u32 a0h = hh[2 * kt][0],     a1h = hh[2 * kt][1];
                const u32 a2h = hh[2 * kt + 1][0], a3h = hh[2 * kt + 1][1];
                const u32 a0l = hl[2 * kt][0],     a1l = hl[2 * kt][1];
                const u32 a2l = hl[2 * kt + 1][0], a3l = hl[2 * kt + 1][1];
#pragma unroll
                for (int nt = 0; nt < 32; ++nt) {
                    const uint4 bf = *(const uint4*)(smem + OFF_UF + ((nt * 4 + kt) * 32 + lane) * 16);
                    mma16816(acc[nt], a0h, a1h, a2h, a3h, bf.x, bf.y);   // h_hi*U_hi
                    mma16816(acc[nt], a0h, a1h, a2h, a3h, bf.z, bf.w);   // h_hi*U_lo
                    mma16816(acc[nt], a0l, a1l, a2l, a3l, bf.x, bf.y);   // h_lo*U_hi
                }
            }
        }

        // ---- epilogue: gates -> c,h; h packed into next A frags (registers) ----
        const bool last = (t == 4);
#pragma unroll
        for (int q = 0; q < 8; ++q)
#pragma unroll
            for (int r2 = 0; r2 < 2; ++r2) {
                float hv[2];
#pragma unroll
                for (int e = 0; e < 2; ++e) {
                    const int ix = 2 * r2 + e;
                    const float zi = acc[q][ix];        // gate i: n-tiles 0..7
                    const float zf = acc[8 + q][ix];    // gate f
                    const float zg = acc[16 + q][ix];   // gate g
                    const float zo = acc[24 + q][ix];   // gate o
                    const float ig = sigm(zi), fg = sigm(zf);
                    const float gg = tanh_hw(zg), og = sigm(zo);
                    const int cid = (q << 2) | (e << 1) | r2;
                    const float cn = fmaf(fg, c[cid], ig * gg);
                    c[cid] = cn;
                    hv[e] = og * tanh_hw(cn);
                }
                if (!last) {
                    const unsigned short h0 = f2bf(hv[0]), h1 = f2bf(hv[1]);
                    const unsigned short l0 = f2bf(hv[0] - bf2f(h0));
                    const unsigned short l1 = f2bf(hv[1] - bf2f(h1));
                    hh[q][r2] = packbf(h0, h1);
                    hl[q][r2] = packbf(l0, l1);
                } else {
                    const float2 wd2 = *(const float2*)(sWd + 8 * q + 2 * tg);
                    pd[r2] = fmaf(hv[0], wd2.x, fmaf(hv[1], wd2.y, pd[r2]));
                }
            }
    }

    // ---- Dense(1, relu): reduce over the 4 tg-lanes of each quad (shuffles only) ----
#pragma unroll
    for (int r2 = 0; r2 < 2; ++r2) {
        pd[r2] += __shfl_xor_sync(0xFFFFFFFFu, pd[r2], 1);
        pd[r2] += __shfl_xor_sync(0xFFFFFFFFu, pd[r2], 2);
    }
    if (tg == 0) {
        const float bdv = __ldg(bd);
        const long orow0 = rowBase + r0 + gid;
        const long orow1 = orow0 + 8;
        if (orow0 < Bn) out[orow0] = fmaxf(pd[0] + bdv, 0.f);
        if (orow1 < Bn) out[orow1] = fmaxf(pd[1] + bdv, 0.f);
    }
}

extern "C" void kernel_launch(void* const* d_in, const int* in_sizes, int n_in,
                              void* d_out, int out_size) {
    const float* x  = (const float*)d_in[0];
    const float* W  = (const float*)d_in[1];
    const float* U  = (const float*)d_in[2];
    const float* b  = (const float*)d_in[3];
    const float* Wd = (const float*)d_in[4];
    const float* bd = (const float*)d_in[5];
    float* out = (float*)d_out;

    const int Bn = in_sizes[0] / 5;      // x is [B, 5, 1]
    cudaFuncSetAttribute(lstm_mma, cudaFuncAttributeMaxDynamicSharedMemorySize, SMEM_BYTES);

    const int grid = (Bn + ROWS - 1) / ROWS;
    lstm_mma<<<grid, TPB, SMEM_BYTES>>>(x, W, U, b, Wd, bd, out, Bn);
}

// round 16
// speedup vs baseline: 1.2176x; 1.2176x over previous
#include <cuda_runtime.h>
#include <cuda_bf16.h>

#define TPB   128
#define ROWS  64          // batch rows per CTA; 16 rows per warp (warp-private recurrence)

typedef unsigned int u32;

// ---------- helpers ----------
__device__ __forceinline__ unsigned short f2bf(float f) {
    unsigned short u; asm("cvt.rn.bf16.f32 %0, %1;" : "=h"(u) : "f"(f)); return u;
}
__device__ __forceinline__ float bf2f(unsigned short u) { return __uint_as_float((u32)u << 16); }
__device__ __forceinline__ u32 packbf(unsigned short lo, unsigned short hi) {
    return (u32)lo | ((u32)hi << 16);
}
__device__ __forceinline__ float tanh_hw(float x) {
    float y; asm("tanh.approx.f32 %0, %1;" : "=f"(y) : "f"(x)); return y;
}
__device__ __forceinline__ float sigm(float x) {   // sigma(x) = 0.5 + 0.5*tanh(x/2)
    return fmaf(0.5f, tanh_hw(0.5f * x), 0.5f);
}
// m16n8k16 bf16 MMA, f32 accum (HMMA path on sm_103)
__device__ __forceinline__ void mma16816(float* d, u32 a0, u32 a1, u32 a2, u32 a3,
                                         u32 b0, u32 b1) {
    asm volatile("mma.sync.aligned.m16n8k16.row.col.f32.bf16.bf16.f32 "
                 "{%0,%1,%2,%3}, {%4,%5,%6,%7}, {%8,%9}, {%0,%1,%2,%3};"
                 : "+f"(d[0]), "+f"(d[1]), "+f"(d[2]), "+f"(d[3])
                 : "r"(a0), "r"(a1), "r"(a2), "r"(a3), "r"(b0), "r"(b1));
}

// SMEM byte offsets
#define OFF_UF   0                       // frag-linear U (hi+lo): 32nt x 4kt x 32 lanes x 16B = 65536
#define OFF_SW   65536                   // W[256] f32
#define OFF_SB   (OFF_SW + 1024)         // b[256] f32
#define OFF_SWD  (OFF_SB + 1024)         // Wd[64] f32
#define OFF_SX   (OFF_SWD + 256)         // x[64*5] f32
#define SMEM_BYTES (OFF_SX + 1280)       // 69120 B -> 3 CTAs/SM

__global__ void __launch_bounds__(TPB, 3)
lstm_mma(const float* __restrict__ x, const float* __restrict__ W,
         const float* __restrict__ U, const float* __restrict__ b,
         const float* __restrict__ Wd, const float* __restrict__ bd,
         float* __restrict__ out, int Bn)
{
    extern __shared__ char smem[];
    float* sW  = (float*)(smem + OFF_SW);
    float* sB  = (float*)(smem + OFF_SB);
    float* sWd = (float*)(smem + OFF_SWD);
    float* sX  = (float*)(smem + OFF_SX);

    const int tid  = threadIdx.x;
    const int lane = tid & 31;
    const int wid  = tid >> 5;           // 4 warps, each owns 16 rows
    const int gid  = lane >> 2;
    const int tg   = lane & 3;
    const int r0   = wid * 16;
    const long rowBase = (long)blockIdx.x * ROWS;

    // ---- stage: frag-linear U (hi/lo bf16), W, b, Wd, x ----
    for (int idx = tid; idx < 4096; idx += TPB) {
        const int N  = idx >> 7;         // n-tile 0..31
        const int kt = (idx >> 5) & 3;   // k-tile 0..3
        const int l  = idx & 31;
        const int g2 = l >> 2, t2 = l & 3;
        const int col = N * 8 + g2;
        const int k0  = kt * 16 + 2 * t2;
        const float u0 = U[k0 * 256 + col],       u1 = U[(k0 + 1) * 256 + col];
        const float u8 = U[(k0 + 8) * 256 + col], u9 = U[(k0 + 9) * 256 + col];
        const unsigned short h0 = f2bf(u0), h1 = f2bf(u1), h8 = f2bf(u8), h9 = f2bf(u9);
        const unsigned short l0 = f2bf(u0 - bf2f(h0)), l1 = f2bf(u1 - bf2f(h1));
        const unsigned short l8 = f2bf(u8 - bf2f(h8)), l9 = f2bf(u9 - bf2f(h9));
        uint4 v;
        v.x = packbf(h0, h1);  v.y = packbf(h8, h9);   // B_hi frag regs
        v.z = packbf(l0, l1);  v.w = packbf(l8, l9);   // B_lo frag regs
        *(uint4*)(smem + OFF_UF + idx * 16) = v;
    }
    for (int i = tid; i < 256; i += TPB) { sW[i] = W[i]; sB[i] = b[i]; }
    if (tid < 64) sWd[tid] = Wd[tid];
    {
        const float* xs = x + rowBase * 5;
        for (int i = tid; i < ROWS * 5; i += TPB)
            if (rowBase * 5 + i < (long)Bn * 5) sX[i] = xs[i];
    }
    __syncthreads();                     // the ONLY barrier in the kernel

    float c[32];                         // c[(q<<2)|(e<<1)|r2]
#pragma unroll
    for (int i = 0; i < 32; ++i) c[i] = 0.f;
    u32 hh[8][2], hl[8][2];              // h as A-frags (hi/lo bf16), current step
    float pd[2] = {0.f, 0.f};            // dense partials (rows gid, gid+8)

#pragma unroll 1
    for (int t = 0; t < 5; ++t) {
        const bool last = (t == 4);
        const float xr0 = sX[(r0 + gid) * 5 + t];
        const float xr1 = sX[(r0 + gid + 8) * 5 + t];
        u32 hhn[8][2], hln[8][2];        // next-step A-frags

        // ---- gate-group blocked: MMA(q) then epilogue(q); epilogue(q) MUFUs
        //      overlap MMA(q+1) in the issue stream (no cross dependence) ----
#pragma unroll
        for (int q = 0; q < 8; ++q) {
            // acc init: z = x*W + b for nt in {q, 8+q, 16+q, 24+q}
            float acc4[4][4];
#pragma unroll
            for (int g = 0; g < 4; ++g) {
                const int nt = 8 * g + q;
                const float2 w2 = *(const float2*)(sW + 8 * nt + 2 * tg);
                const float2 b2 = *(const float2*)(sB + 8 * nt + 2 * tg);
                acc4[g][0] = fmaf(xr0, w2.x, b2.x);
                acc4[g][1] = fmaf(xr0, w2.y, b2.y);
                acc4[g][2] = fmaf(xr1, w2.x, b2.x);
                acc4[g][3] = fmaf(xr1, w2.y, b2.y);
            }

            if (t > 0) {
#pragma unroll
                for (int kt = 0; kt < 4; ++kt) {
                    const u32 a0h = hh[2 * kt][0],     a1h = hh[2 * kt][1];
                    const u32 a2h = hh[2 * kt + 1][0], a3h = hh[2 * kt + 1][1];
                    const u32 a0l = hl[2 * kt][0],     a1l = hl[2 * kt][1];
                    const u32 a2l = hl[2 * kt + 1][0], a3l = hl[2 * kt + 1][1];
#pragma unroll
                    for (int g = 0; g < 4; ++g) {
                        const int nt = 8 * g + q;
                        const uint4 bf = *(const uint4*)(smem + OFF_UF + ((nt * 4 + kt) * 32 + lane) * 16);
                        mma16816(acc4[g], a0h, a1h, a2h, a3h, bf.x, bf.y);   // h_hi*U_hi
                        mma16816(acc4[g], a0h, a1h, a2h, a3h, bf.z, bf.w);   // h_hi*U_lo
                        mma16816(acc4[g], a0l, a1l, a2l, a3l, bf.x, bf.y);   // h_lo*U_hi
                    }
                }
            }

            // epilogue for group q: gates -> c,h -> next A-frag registers
#pragma unroll
            for (int r2 = 0; r2 < 2; ++r2) {
                float hv[2];
#pragma unroll
                for (int e = 0; e < 2; ++e) {
                    const int ix = 2 * r2 + e;
                    const float zi = acc4[0][ix];
                    const float zf = acc4[1][ix];
                    const float zg = acc4[2][ix];
                    const float zo = acc4[3][ix];
                    const float ig = sigm(zi), fg = sigm(zf);
                    const float gg = tanh_hw(zg), og = sigm(zo);
                    const int cid = (q << 2) | (e << 1) | r2;
                    const float cn = fmaf(fg, c[cid], ig * gg);
                    c[cid] = cn;
                    hv[e] = og * tanh_hw(cn);
                }
                if (!last) {
                    const unsigned short h0 = f2bf(hv[0]), h1 = f2bf(hv[1]);
                    const unsigned short l0 = f2bf(hv[0] - bf2f(h0));
                    const unsigned short l1 = f2bf(hv[1] - bf2f(h1));
                    hhn[q][r2] = packbf(h0, h1);
                    hln[q][r2] = packbf(l0, l1);
                } else {
                    const float2 wd2 = *(const float2*)(sWd + 8 * q + 2 * tg);
                    pd[r2] = fmaf(hv[0], wd2.x, fmaf(hv[1], wd2.y, pd[r2]));
                }
            }
        }

        if (!last) {
#pragma unroll
            for (int q = 0; q < 8; ++q) {
                hh[q][0] = hhn[q][0];  hh[q][1] = hhn[q][1];
                hl[q][0] = hln[q][0];  hl[q][1] = hln[q][1];
            }
        }
    }

    // ---- Dense(1, relu): reduce over the 4 tg-lanes of each quad ----
#pragma unroll
    for (int r2 = 0; r2 < 2; ++r2) {
        pd[r2] += __shfl_xor_sync(0xFFFFFFFFu, pd[r2], 1);
        pd[r2] += __shfl_xor_sync(0xFFFFFFFFu, pd[r2], 2);
    }
    if (tg == 0) {
        const float bdv = __ldg(bd);
        const long orow0 = rowBase + r0 + gid;
        const long orow1 = orow0 + 8;
        if (orow0 < Bn) out[orow0] = fmaxf(pd[0] + bdv, 0.f);
        if (orow1 < Bn) out[orow1] = fmaxf(pd[1] + bdv, 0.f);
    }
}

extern "C" void kernel_launch(void* const* d_in, const int* in_sizes, int n_in,
                              void* d_out, int out_size) {
    const float* x  = (const float*)d_in[0];
    const float* W  = (const float*)d_in[1];
    const float* U  = (const float*)d_in[2];
    const float* b  = (const float*)d_in[3];
    const float* Wd = (const float*)d_in[4];
    const float* bd = (const float*)d_in[5];
    float* out = (float*)d_out;

    const int Bn = in_sizes[0] / 5;      // x is [B, 5, 1]
    cudaFuncSetAttribute(lstm_mma, cudaFuncAttributeMaxDynamicSharedMemorySize, SMEM_BYTES);

    const int grid = (Bn + ROWS - 1) / ROWS;
    lstm_mma<<<grid, TPB, SMEM_BYTES>>>(x, W, U, b, Wd, bd, out, Bn);
}